// round 10
// baseline (speedup 1.0000x reference)
#include <cuda_runtime.h>
#include <cuda_bf16.h>
#include <stdint.h>

#define NN 8192
#define DD 128
#define KK 4096         // K = N/2
#define NKEEP (NN - KK) // 4096
#define NB  512         // persistent grid; co-resident (4 blocks/SM cap, 592 >= 512)
#define LCAP 32         // per-node edge-list capacity (max out-deg ~10 for this input)

typedef unsigned long long u64;
typedef unsigned int u32;

// ---------------- device scratch ------------------------------------------
__device__ u32   g_list[NN * LCAP]; // per-node raw neighbor appends
__device__ int   g_cnt[NN];         // raw list length; zero on entry, restored in D
__device__ float g_dinvf[NN];       // deg^-0.5 (f32), 0 if deg==0
__device__ int   g_rank[NN];        // zeroed in B2 before C's atomics
__device__ float g_norm[NN];
__device__ float g_wf[NN];
__device__ u32   g_mw[NN];          // ascending key: smaller = higher weight
__device__ int   g_ei[NN];
__device__ int   g_ej[NN];
__device__ int   g_is64;
// hierarchical barrier state
__device__ u32   g_leaf[32 * 64];   // 32 counters, 256B apart (distinct LTS lines)
__device__ u32   g_master;
__device__ u32   g_bargen;

// two-level grid barrier: 16 arrivals/leaf, 32 leaves -> master.
// atomic resets + threadfence keep reset ordered before next-level add;
// acquire fence after wake invalidates stale L1 lines before post-barrier loads.
__device__ __forceinline__ void grid_barrier() {
    __syncthreads();
    if (threadIdx.x == 0) {
        __threadfence();                                  // release
        u32 gen = ((volatile u32*)&g_bargen)[0];
        int leaf = (blockIdx.x & 31) * 64;
        if (atomicAdd(&g_leaf[leaf], 1u) == (NB / 32) - 1) {
            atomicExch(&g_leaf[leaf], 0u);
            __threadfence();
            if (atomicAdd(&g_master, 1u) == 31) {
                atomicExch(&g_master, 0u);
                __threadfence();
                atomicAdd(&g_bargen, 1u);                 // release barrier
            }
        }
        while (((volatile u32*)&g_bargen)[0] == gen) __nanosleep(32);
        __threadfence();                                  // acquire
    }
    __syncthreads();
}

__global__ void __launch_bounds__(256, 4)
mega_kernel(const float* __restrict__ x,
            const void* __restrict__ edges,
            const void* __restrict__ batch,
            float* __restrict__ out) {
    __shared__ union {
        u64 sk[512];                                  // phase C key chunk (4KB)
        struct { u32 words[256]; int wpref[256]; int warpsum[8]; } em;
    } sh;

    int tid  = threadIdx.x;
    int wid  = tid >> 5;
    int lane = tid & 31;
    int bid  = blockIdx.x;

    // ============ Phase A: norms + edge decode + list append ==============
    #pragma unroll
    for (int rep = 0; rep < 2; rep++) {
        int row = bid * 16 + wid * 2 + rep;
        const float4* rp = (const float4*)(x + (size_t)row * DD);
        float4 v = rp[lane];
        double s = (double)v.x * v.x + (double)v.y * v.y + (double)v.z * v.z + (double)v.w * v.w;
        #pragma unroll
        for (int o = 16; o > 0; o >>= 1) s += __shfl_down_sync(0xffffffffu, s, o);
        if (lane == 0) g_norm[row] = (float)sqrt(s);
    }

    if (wid == 0) {
        // dtype detect: odd 32-bit words of first 64 entries all zero <=> int64
        const u32* e32 = (const u32*)edges;
        u32 odd = e32[2 * lane + 1] | e32[2 * (lane + 32) + 1];
        int is64 = !__any_sync(0xffffffffu, odd != 0u);
        if (bid == 0 && lane == 0) g_is64 = is64;

        if (lane < 16) {                       // 16 edges per block
            int e = bid * 16 + lane;
            int i, j;
            if (is64) {
                const long long* p = (const long long*)edges;
                i = (int)p[e];
                j = (int)p[NN + e];
            } else {
                const int* p = (const int*)edges;
                i = p[e];
                j = p[NN + e];
            }
            g_ei[e] = i;
            g_ej[e] = j;
            int pos = atomicAdd(&g_cnt[i], 1);
            if (pos < LCAP) g_list[i * LCAP + pos] = (u32)j;
        }
    }

    grid_barrier();

    // ============ Phase B1: warp sort + dedup (registers persist to B2) ===
    u32 vset[2];        // sorted values per lane
    u32 uset[2];        // ballot of unique lanes (uniform in warp)
    #pragma unroll
    for (int rep = 0; rep < 2; rep++) {
        int node = bid * 16 + wid * 2 + rep;
        int cnt = g_cnt[node];
        u32 v = (lane < cnt) ? g_list[node * LCAP + lane] : 0xFFFFFFFFu;
        // 32-wide bitonic sort (ascending)
        #pragma unroll
        for (int k = 2; k <= 32; k <<= 1) {
            #pragma unroll
            for (int j = k >> 1; j > 0; j >>= 1) {
                u32 o = __shfl_xor_sync(0xffffffffu, v, j);
                bool up  = ((lane & k) == 0);
                bool low = ((lane & j) == 0);
                u32 mn = v < o ? v : o;
                u32 mx = v < o ? o : v;
                v = (up == low) ? mn : mx;
            }
        }
        u32 prev = __shfl_up_sync(0xffffffffu, v, 1);
        bool uniq = (v != 0xFFFFFFFFu) && (lane == 0 || v != prev);
        u32 um = __ballot_sync(0xffffffffu, uniq);
        int deg = __popc(um);
        vset[rep] = v;
        uset[rep] = um;
        if (lane == 0)
            g_dinvf[node] = (deg > 0) ? (float)(1.0 / sqrt((double)deg)) : 0.0f;
    }

    grid_barrier();

    // ============ Phase B2: weights (ascending-j, R3-R9 numerics) =========
    #pragma unroll 1
    for (int rep = 0; rep < 2; rep++) {
        int node = bid * 16 + wid * 2 + rep;
        float ni = fmaxf(g_norm[node], 1e-12f);
        float4 a = ((const float4*)(x + (size_t)node * DD))[lane];
        float ax = a.x / ni, ay = a.y / ni, az = a.z / ni, aw = a.w / ni;

        double acc = 0.0;
        u32 m = uset[rep];                       // uniform: set bits asc = j asc
        #pragma unroll 1
        while (m) {
            int src = __ffs(m) - 1;
            m &= m - 1;
            int j = (int)__shfl_sync(0xffffffffu, vset[rep], src);
            float nj = fmaxf(g_norm[j], 1e-12f);
            float4 bv = ((const float4*)(x + (size_t)j * DD))[lane];
            float bx = bv.x / nj, by = bv.y / nj, bz = bv.z / nj, bw = bv.w / nj;
            double sd = (double)ax * bx + (double)ay * by + (double)az * bz + (double)aw * bw;
            #pragma unroll
            for (int o = 16; o > 0; o >>= 1) sd += __shfl_down_sync(0xffffffffu, sd, o);
            if (lane == 0) acc += sd * (double)g_dinvf[j];
        }
        if (lane == 0) {
            float wf = (float)((double)g_dinvf[node] * acc);
            g_wf[node] = wf;
            u32 u = __float_as_uint(wf);
            u32 mm = (u & 0x80000000u) ? ~u : (u | 0x80000000u);
            g_mw[node] = ~mm;      // smaller = larger weight -> rank asc = topk order
            g_rank[node] = 0;      // reset before phase C atomics
        }
    }

    grid_barrier();

    // ============ Phase C: rank = #{keys < mine} ===========================
    {
        int bn = bid & 31;                 // node chunk (256 nodes)
        int bj = bid >> 5;                 // key chunk (512 keys)
        int jbase = bj * 512;
        #pragma unroll
        for (int q = 0; q < 2; q++) {
            int i = tid + q * 256;
            int j = jbase + i;
            sh.sk[i] = ((u64)g_mw[j] << 13) | (u32)j;
        }
        __syncthreads();

        int node = bn * 256 + tid;
        u64 my = ((u64)g_mw[node] << 13) | (u32)node;
        int cnt = 0;
        const ulonglong2* sk2 = (const ulonglong2*)sh.sk;
        #pragma unroll 8
        for (int i = 0; i < 256; i++) {    // broadcast LDS.128: 2 keys/load
            ulonglong2 p = sk2[i];
            cnt += (p.x < my) + (p.y < my);
        }
        atomicAdd(&g_rank[node], cnt);     // integer: deterministic
    }

    grid_barrier();

    // ============ Phase D: gather + emit + invariant restore ==============
    // gather: warp per node; output row == rank
    #pragma unroll
    for (int rep = 0; rep < 2; rep++) {
        int node = bid * 16 + wid * 2 + rep;
        int r = g_rank[node];
        if (r < KK) {
            float4 v = ((const float4*)(x + (size_t)node * DD))[lane];
            ((float4*)(out + (size_t)r * DD))[lane] = v;
            if (lane == 0) {
                const int OFF_PERM  = KK * DD + 2 * NKEEP;
                const int OFF_BATCH = OFF_PERM + KK;
                const int OFF_W     = OFF_BATCH + KK;
                long long bv;
                if (g_is64) bv = ((const long long*)batch)[node];
                else        bv = (long long)((const int*)batch)[node];
                out[OFF_PERM + r]  = (float)node;
                out[OFF_BATCH + r] = (float)bv;
                out[OFF_W + r]     = g_wf[node];
            }
        }
    }

    // emit: blocks 0..31 (unselected-bitmap + popcount prefix; 256 slots each)
    if (bid < 32) {
        #pragma unroll
        for (int q = 0; q < 32; q++) {
            int n2 = q * 256 + tid;
            int uns = (g_rank[n2] >= KK) ? 1 : 0;
            u32 w = __ballot_sync(0xffffffffu, uns);
            if (lane == 0) sh.em.words[q * 8 + wid] = w;
        }
        __syncthreads();

        int c = __popc(sh.em.words[tid]);
        int v = c;
        #pragma unroll
        for (int o = 1; o < 32; o <<= 1) {
            int t = __shfl_up_sync(0xffffffffu, v, o);
            if (lane >= o) v += t;
        }
        if (lane == 31) sh.em.warpsum[wid] = v;
        __syncthreads();
        if (wid == 0) {
            int s = (lane < 8) ? sh.em.warpsum[lane] : 0;
            #pragma unroll
            for (int o = 1; o < 8; o <<= 1) {
                int t = __shfl_up_sync(0xffffffffu, s, o);
                if (lane >= o) s += t;
            }
            if (lane < 8) sh.em.warpsum[lane] = s;
        }
        __syncthreads();
        sh.em.wpref[tid] = v - c + ((wid > 0) ? sh.em.warpsum[wid - 1] : 0);
        __syncthreads();

        int i = bid * 256 + tid;
        if (g_rank[i] >= KK) {               // kept edge slot
            int word = i >> 5;
            u32 w = sh.em.words[word];
            int pos = sh.em.wpref[word] + __popc(w & ((1u << (i & 31)) - 1u));
            int a = g_ei[i], b = g_ej[i];
            int ra = g_rank[a], rb = g_rank[b];
            const int OFF_E = KK * DD;
            out[OFF_E + pos]         = (float)((ra < KK) ? ra : 0);
            out[OFF_E + NKEEP + pos] = (float)((rb < KK) ? rb : 0);
        }
    }

    // restore zero-invariant: blocks 480..511 clear g_cnt (8192 ints)
    if (bid >= NB - 32) {
        int n = (bid - (NB - 32)) * 256 + tid;
        g_cnt[n] = 0;
    }
}

// ---------------- launch ----------------
extern "C" void kernel_launch(void* const* d_in, const int* in_sizes, int n_in,
                              void* d_out, int out_size) {
    const float* x     = (const float*)d_in[0];
    const void*  edges = d_in[1];
    const void*  batch = d_in[2];
    float* out = (float*)d_out;

    mega_kernel<<<NB, 256>>>(x, edges, batch, out);
}

// round 11
// speedup vs baseline: 1.2768x; 1.2768x over previous
#include <cuda_runtime.h>
#include <cuda_bf16.h>
#include <stdint.h>

#define NN 8192
#define DD 128
#define KK 4096         // K = N/2
#define NKEEP (NN - KK) // 4096
#define WPR 256         // 32-bit words per adjacency row
#define LCAP 32         // per-node unique-neighbor capacity (max out-deg ~10 here)

typedef unsigned long long u64;
typedef unsigned int u32;

// ---------------- device scratch (zero at load; invariants restored by k45)
__device__ u32   g_adj[NN * WPR];   // dup-detect bitmap; zero on entry
__device__ u32   g_list[NN * LCAP]; // unique neighbors (racy order; sorted in k3)
__device__ int   g_cnt[NN];         // unique out-degree; zero on entry
__device__ int   g_rank[NN];        // zeroed in k3 before k4a atomics
__device__ float g_norm[NN];
__device__ float g_wf[NN];
__device__ u32   g_mw[NN];          // ascending key: smaller = higher weight
__device__ int   g_ei[NN];
__device__ int   g_ej[NN];
__device__ int   g_is64;

// ============ K1: norms + edge decode + dup-detect + unique append ========
__global__ void k1_norms_pack(const float* __restrict__ x,
                              const void* __restrict__ edges) {
    int tid  = threadIdx.x;
    int wid  = tid >> 5;
    int lane = tid & 31;
    int row  = blockIdx.x * 8 + wid;

    // norms: warp per row, double sumsq
    const float4* rp = (const float4*)(x + (size_t)row * DD);
    float4 v = rp[lane];
    double s = (double)v.x * v.x + (double)v.y * v.y + (double)v.z * v.z + (double)v.w * v.w;
    #pragma unroll
    for (int o = 16; o > 0; o >>= 1) s += __shfl_down_sync(0xffffffffu, s, o);
    if (lane == 0) g_norm[row] = (float)sqrt(s);

    // blocks 0..31: decode 256 edges each
    if (blockIdx.x < 32) {
        // per-warp dtype detect: odd 32-bit words of first 64 entries all zero <=> int64
        const u32* e32 = (const u32*)edges;
        u32 odd = e32[2 * lane + 1] | e32[2 * (lane + 32) + 1];
        int is64 = !__any_sync(0xffffffffu, odd != 0u);
        if (blockIdx.x == 0 && tid == 0) g_is64 = is64;

        int e = blockIdx.x * 256 + tid;
        int i, j;
        if (is64) {
            const long long* p = (const long long*)edges;
            i = (int)p[e];
            j = (int)p[NN + e];
        } else {
            const int* p = (const int*)edges;
            i = p[e];
            j = p[NN + e];
        }
        g_ei[e] = i;
        g_ej[e] = j;
        u32 bit = 1u << (j & 31);
        u32 old = atomicOr(&g_adj[i * WPR + (j >> 5)], bit);
        if (!(old & bit)) {                          // first setter owns unique edge
            int pos = atomicAdd(&g_cnt[i], 1);
            if (pos < LCAP) g_list[i * LCAP + pos] = (u32)j;
        }
    }
}

// ============ K3: warp sort list + weights (R6-identical numerics) ========
__global__ void k3_weights(const float* __restrict__ x) {
    int tid  = threadIdx.x;
    int wid  = tid >> 5;
    int lane = tid & 31;
    int node = blockIdx.x * 8 + wid;

    int cnt = g_cnt[node];                           // unique out-degree
    u32 v = (lane < cnt) ? g_list[node * LCAP + lane] : 0xFFFFFFFFu;
    // 32-wide bitonic sort (ascending) — erases racy append order
    #pragma unroll
    for (int k = 2; k <= 32; k <<= 1) {
        #pragma unroll
        for (int j = k >> 1; j > 0; j >>= 1) {
            u32 o = __shfl_xor_sync(0xffffffffu, v, j);
            bool up  = ((lane & k) == 0);
            bool low = ((lane & j) == 0);
            u32 mn = v < o ? v : o;
            u32 mx = v < o ? o : v;
            v = (up == low) ? mn : mx;
        }
    }

    float ni = fmaxf(g_norm[node], 1e-12f);
    float4 a = ((const float4*)(x + (size_t)node * DD))[lane];
    float ax = a.x / ni, ay = a.y / ni, az = a.z / ni, aw = a.w / ni;

    double acc = 0.0;
    #pragma unroll 1
    for (int ss = 0; ss < cnt; ss++) {               // ascending j (sorted)
        int j = (int)__shfl_sync(0xffffffffu, v, ss);
        float nj = fmaxf(g_norm[j], 1e-12f);
        float4 bv = ((const float4*)(x + (size_t)j * DD))[lane];
        float bx = bv.x / nj, by = bv.y / nj, bz = bv.z / nj, bw = bv.w / nj;
        double sd = (double)ax * bx + (double)ay * by + (double)az * bz + (double)aw * bw;
        #pragma unroll
        for (int o = 16; o > 0; o >>= 1) sd += __shfl_down_sync(0xffffffffu, sd, o);
        if (lane == 0) {
            int dj = g_cnt[j];
            float dinvj = (dj > 0) ? (float)(1.0 / sqrt((double)dj)) : 0.0f;
            acc += sd * (double)dinvj;               // identical numerics to R3-R10
        }
    }
    if (lane == 0) {
        float dinvn = (cnt > 0) ? (float)(1.0 / sqrt((double)cnt)) : 0.0f;
        float wf = (float)((double)dinvn * acc);
        g_wf[node] = wf;
        u32 u = __float_as_uint(wf);
        u32 m = (u & 0x80000000u) ? ~u : (u | 0x80000000u);
        g_mw[node] = ~m;       // smaller = larger weight -> rank asc = topk order
        g_rank[node] = 0;      // reset before k4a atomics (replay invariant)
    }
}

// ============ K4a: direct rank computation ================================
// blockIdx: low 5 bits = node chunk (256 nodes), high 3 bits = j chunk (1024 keys)
__global__ void k4a_rank() {
    __shared__ u64 sk[1024];
    int tid = threadIdx.x;                   // 256 threads
    int bn = blockIdx.x & 31;
    int bj = blockIdx.x >> 5;
    int jbase = bj * 1024;
    #pragma unroll
    for (int q = 0; q < 4; q++) {
        int i = tid + q * 256;
        int j = jbase + i;
        sk[i] = ((u64)g_mw[j] << 13) | (u32)j;
    }
    __syncthreads();

    int node = bn * 256 + tid;
    u64 my = ((u64)g_mw[node] << 13) | (u32)node;
    int cnt = 0;
    const ulonglong2* sk2 = (const ulonglong2*)sk;
    #pragma unroll 8
    for (int i = 0; i < 512; i++) {          // broadcast LDS.128: 2 keys/load
        ulonglong2 p = sk2[i];
        cnt += (p.x < my) + (p.y < my);
    }
    atomicAdd(&g_rank[node], cnt);           // integer: deterministic
}

// ============ K45: fused emit + gather + invariant restore ================
__global__ void k45_emit_gather(const float* __restrict__ x,
                                const void* __restrict__ batch,
                                float* __restrict__ out) {
    int tid  = threadIdx.x;
    int lane = tid & 31;
    int wid  = tid >> 5;

    // ---- gather: warp per node; output row == rank ----
    int node = blockIdx.x * 8 + wid;
    int r = g_rank[node];
    if (r < KK) {
        float4 v = ((const float4*)(x + (size_t)node * DD))[lane];
        ((float4*)(out + (size_t)r * DD))[lane] = v;
        if (lane == 0) {
            const int OFF_PERM  = KK * DD + 2 * NKEEP;
            const int OFF_BATCH = OFF_PERM + KK;
            const int OFF_W     = OFF_BATCH + KK;
            long long bv;
            if (g_is64) bv = ((const long long*)batch)[node];
            else        bv = (long long)((const int*)batch)[node];
            out[OFF_PERM + r]  = (float)node;
            out[OFF_BATCH + r] = (float)bv;
            out[OFF_W + r]     = g_wf[node];
        }
    }

    // ---- emit: blocks 0..31 ----
    if (blockIdx.x < 32) {
        __shared__ u32 words[256];
        __shared__ int wpref[256];
        __shared__ int warpsum[8];

        #pragma unroll
        for (int q = 0; q < 32; q++) {
            int n2 = q * 256 + tid;
            int uns = (g_rank[n2] >= KK) ? 1 : 0;
            u32 w = __ballot_sync(0xffffffffu, uns);
            if (lane == 0) words[q * 8 + wid] = w;
        }
        __syncthreads();

        int c = __popc(words[tid]);
        int v = c;
        #pragma unroll
        for (int o = 1; o < 32; o <<= 1) {
            int t = __shfl_up_sync(0xffffffffu, v, o);
            if (lane >= o) v += t;
        }
        if (lane == 31) warpsum[wid] = v;
        __syncthreads();
        if (wid == 0) {
            int s = (lane < 8) ? warpsum[lane] : 0;
            #pragma unroll
            for (int o = 1; o < 8; o <<= 1) {
                int t = __shfl_up_sync(0xffffffffu, s, o);
                if (lane >= o) s += t;
            }
            if (lane < 8) warpsum[lane] = s;
        }
        __syncthreads();
        wpref[tid] = v - c + ((wid > 0) ? warpsum[wid - 1] : 0);
        __syncthreads();

        int i = blockIdx.x * 256 + tid;
        if (g_rank[i] >= KK) {               // kept edge slot
            int word = i >> 5;
            u32 w = words[word];
            int pos = wpref[word] + __popc(w & ((1u << (i & 31)) - 1u));
            int a = g_ei[i], b = g_ej[i];
            int ra = g_rank[a], rb = g_rank[b];
            const int OFF_E = KK * DD;
            out[OFF_E + pos]         = (float)((ra < KK) ? ra : 0);
            out[OFF_E + NKEEP + pos] = (float)((rb < KK) ? rb : 0);
        }
    }

    // ---- restore zero-invariants: blocks 992..1023 ----
    if (blockIdx.x >= 992) {
        int e = (blockIdx.x - 992) * 256 + tid;
        g_adj[g_ei[e] * WPR + (g_ej[e] >> 5)] = 0u;
        g_cnt[e] = 0;
    }
}

// ---------------- launch ----------------
extern "C" void kernel_launch(void* const* d_in, const int* in_sizes, int n_in,
                              void* d_out, int out_size) {
    const float* x     = (const float*)d_in[0];
    const void*  edges = d_in[1];
    const void*  batch = d_in[2];
    float* out = (float*)d_out;

    k1_norms_pack<<<1024, 256>>>(x, edges);
    k3_weights<<<1024, 256>>>(x);
    k4a_rank<<<256, 256>>>();
    k45_emit_gather<<<1024, 256>>>(x, batch, out);
}